// round 1
// baseline (speedup 1.0000x reference)
#include <cuda_runtime.h>
#include <math.h>

// Problem constants
#define BATCH 32
#define CIN   8
#define COUT  8
#define KP    4
#define DIN   16
#define DOUT  16
#define SS_   32
#define EPSV  1e-5f

#define NPTS  (BATCH*SS_*SS_)      // 32768 spatial points (b,y,x)
#define NOC   (CIN*COUT*DOUT)      // 1024 conv output channels
#define KDIM  (DIN*9)              // 144 GEMM K
#define OD    (COUT*DOUT)          // 128 (o,d) pairs per point

// ---------------- scratch (device globals; no allocations allowed) -------
__device__ __align__(128) float g_Wk[KDIM*NOC];              // transposed conv weights [k][oc]
__device__ __align__(128) float g_votes[NPTS*NOC];           // conv output, channel-last [pt][oc]  (134MB)
__device__ __align__(128) float g_sumAtt[NPTS*OD];           // routing sum (pre-scale) [pt][o*16+d]
__device__ __align__(128) float g_pmax[NPTS*OD];
__device__ __align__(128) float g_pmean[NPTS*OD];
__device__ __align__(128) float g_gate[NPTS*OD];
__device__ float g_psumArr[1024*8];
__device__ float g_pssArr[1024*8];
__device__ float g_bnMu[8];
__device__ float g_bnRstd[8];

// ---------------- kernel 0: transpose Wt [oc][k] -> Wk [k][oc] -----------
__global__ void k_transpose(const float* __restrict__ Wt) {
    int idx = blockIdx.x * 256 + threadIdx.x;   // grid 576*256 = 147456 exact
    int k  = idx >> 10;
    int oc = idx & 1023;
    g_Wk[idx] = Wt[oc * KDIM + k];
}

// ---------------- kernel 1: implicit-GEMM conv (3x3, pad1) ---------------
// C[m][n] = sum_k A[m][k]*B[k][n] + bt[n];  m=(b,y,x), n=oc, k=(ci,ky,kx)
// 128x128 tile, 8x8 per thread, BK=8, 256 threads.
__global__ __launch_bounds__(256) void k_conv(const float* __restrict__ caps,
                                              const float* __restrict__ bt) {
    __shared__ __align__(16) float As[8][128];
    __shared__ __align__(16) float Bs[8][128];
    __shared__ float bts[128];
    const int tid = threadIdx.x;
    const int n0 = blockIdx.x * 128;
    const int m0 = blockIdx.y * 128;
    if (tid < 128) bts[tid] = bt[n0 + tid];
    const int tx = tid & 15, ty = tid >> 4;
    const int k_l = tid >> 5;
    const int mq  = (tid & 31) * 4;

    float acc[8][8];
#pragma unroll
    for (int i = 0; i < 8; i++)
#pragma unroll
        for (int j = 0; j < 8; j++) acc[i][j] = 0.f;

    for (int kt = 0; kt < KDIM/8; kt++) {
        __syncthreads();
        // B tile
        float4 bv4 = *(const float4*)(g_Wk + (kt*8 + k_l)*1024 + n0 + mq);
        *(float4*)&Bs[k_l][mq] = bv4;
        // A tile (im2col gather)
        int kg = kt*8 + k_l;
        int ci = kg / 9;
        int r  = kg - ci*9;
        int dy = r/3 - 1;
        int dx = (r - (r/3)*3) - 1;
        const float* cp = caps + ci*1024;   // + b*16384 + y*32 + x
#pragma unroll
        for (int i = 0; i < 4; i++) {
            int m = m0 + mq + i;
            int b = m >> 10, yx = m & 1023;
            int y = yx >> 5, x = yx & 31;
            int yy = y + dy, xx = x + dx;
            float v = 0.f;
            if ((unsigned)yy < 32u && (unsigned)xx < 32u)
                v = cp[b*16384 + yy*32 + xx];
            As[k_l][mq + i] = v;
        }
        __syncthreads();
#pragma unroll
        for (int k = 0; k < 8; k++) {
            float a[8], bb[8];
            *(float4*)&a[0]  = *(const float4*)&As[k][ty*4];
            *(float4*)&a[4]  = *(const float4*)&As[k][64 + ty*4];
            *(float4*)&bb[0] = *(const float4*)&Bs[k][tx*4];
            *(float4*)&bb[4] = *(const float4*)&Bs[k][64 + tx*4];
#pragma unroll
            for (int i = 0; i < 8; i++)
#pragma unroll
                for (int j = 0; j < 8; j++)
                    acc[i][j] += a[i] * bb[j];
        }
    }
    // epilogue: + bias, store channel-last votes
#pragma unroll
    for (int i = 0; i < 8; i++) {
        int row = (i < 4) ? (ty*4 + i) : (64 + ty*4 + i - 4);
        float* outp = g_votes + (m0 + row)*1024 + n0;
#pragma unroll
        for (int jh = 0; jh < 2; jh++) {
            int cb = jh*64 + tx*4;
            float4 o4;
            o4.x = acc[i][jh*4+0] + bts[cb+0];
            o4.y = acc[i][jh*4+1] + bts[cb+1];
            o4.z = acc[i][jh*4+2] + bts[cb+2];
            o4.w = acc[i][jh*4+3] + bts[cb+3];
            *(float4*)(outp + cb) = o4;
        }
    }
}

// ---------------- kernel 2: values + pooling + agreement routing ---------
// Per (pt,o,d): values_m = bv[o][m] + sum_c Wv[o][m][c]*votes[pt][c*128+o*16+d]
// outputs: pooledMax, pooledMean (over all 32 m), sumAtt = sum_c2 atts*mean_k
// (the (1+scale) factor provably cancels in the softmax and is applied later)
__global__ __launch_bounds__(256) void k_route(const float* __restrict__ Wv,
                                               const float* __restrict__ bv) {
    __shared__ __align__(16) float wv_s[2048];
    __shared__ float bv_s[256];
    int tid = threadIdx.x;
    for (int i = tid; i < 2048; i += 256) wv_s[i] = Wv[i];
    if (tid < 256) bv_s[tid] = bv[tid];
    __syncthreads();

    int pt   = blockIdx.x * 8 + (tid >> 5);
    int lane = tid & 31;
    int o    = lane >> 2;          // lane = o*4 + dg  -> offset lane*4 is contiguous
    const float* vp = g_votes + pt * 1024;

    float vt[8][4];
#pragma unroll
    for (int c = 0; c < 8; c++) {
        float4 v4 = *(const float4*)(vp + c*128 + lane*4);
        vt[c][0] = v4.x; vt[c][1] = v4.y; vt[c][2] = v4.z; vt[c][3] = v4.w;
    }

    float ksum[8][4], kss[8][4], pmax[4], psum[4];
#pragma unroll
    for (int c = 0; c < 8; c++)
#pragma unroll
        for (int j = 0; j < 4; j++) { ksum[c][j] = 0.f; kss[c][j] = 0.f; }
#pragma unroll
    for (int j = 0; j < 4; j++) { pmax[j] = -1e30f; psum[j] = 0.f; }

    const float4* wv4 = (const float4*)wv_s;
#pragma unroll
    for (int m = 0; m < 32; m++) {
        float4 wa = wv4[(o*32 + m)*2 + 0];
        float4 wb = wv4[(o*32 + m)*2 + 1];
        float bvv = bv_s[o*32 + m];
        const int c2 = m & 7;
#pragma unroll
        for (int j = 0; j < 4; j++) {
            float v = bvv
                + wa.x*vt[0][j] + wa.y*vt[1][j] + wa.z*vt[2][j] + wa.w*vt[3][j]
                + wb.x*vt[4][j] + wb.y*vt[5][j] + wb.z*vt[6][j] + wb.w*vt[7][j];
            ksum[c2][j] += v;
            kss[c2][j]  += v*v;
            pmax[j] = fmaxf(pmax[j], v);
            psum[j] += v;
        }
    }

    float sA[4], pM[4], pMe[4];
#pragma unroll
    for (int j = 0; j < 4; j++) {
        float mean_c[8], std_c[8];
        float mn = 1e30f;
#pragma unroll
        for (int c2 = 0; c2 < 8; c2++) {
            float mu  = ksum[c2][j] * 0.25f;
            float var = fmaxf(kss[c2][j] * 0.25f - mu*mu, 0.f);
            float sd  = sqrtf(var);
            mean_c[c2] = mu; std_c[c2] = sd;
            mn = fminf(mn, sd);
        }
        float wsum = 0.f, av = 0.f;
#pragma unroll
        for (int c2 = 0; c2 < 8; c2++) {
            float w = (std_c[c2] > 0.f) ? (mn / std_c[c2]) : 1.0f;  // softmax(-log std), stabilized
            wsum += w;
            av   += w * mean_c[c2];
        }
        sA[j]  = av / wsum;
        pM[j]  = pmax[j];
        pMe[j] = psum[j] * (1.f/32.f);
    }
    int off = pt*128 + lane*4;
    *(float4*)(g_sumAtt + off) = make_float4(sA[0], sA[1], sA[2], sA[3]);
    *(float4*)(g_pmax   + off) = make_float4(pM[0], pM[1], pM[2], pM[3]);
    *(float4*)(g_pmean  + off) = make_float4(pMe[0], pMe[1], pMe[2], pMe[3]);
}

// ---------------- kernel 3: 3D gate conv (3x3x3, pad1) + BN partials -----
// thread = (pt, o), computes all 16 d with register blocking over dz.
__global__ __launch_bounds__(256) void k_gate(const float* __restrict__ Ws) {
    __shared__ float ws_s[54];
    __shared__ float bsum[8], bss[8];
    int tid = threadIdx.x;
    if (tid < 54) ws_s[tid] = Ws[tid];
    if (tid < 8) { bsum[tid] = 0.f; bss[tid] = 0.f; }
    __syncthreads();

    int pt = blockIdx.x * 32 + (tid >> 3);
    int o  = tid & 7;
    int b  = pt >> 10, yx = pt & 1023;
    int y  = yx >> 5,  x  = yx & 31;

    float acc[16];
#pragma unroll
    for (int d = 0; d < 16; d++) acc[d] = 0.f;

    for (int dy = -1; dy <= 1; dy++) {
        int yy = y + dy;
        if ((unsigned)yy >= 32u) continue;
        for (int dx = -1; dx <= 1; dx++) {
            int xx = x + dx;
            if ((unsigned)xx >= 32u) continue;
            int base = ((b << 10) + (yy << 5) + xx)*128 + (o << 4);
            const float4* pm = (const float4*)(g_pmax  + base);
            const float4* pn = (const float4*)(g_pmean + base);
            float rmx[16], rmn[16];
#pragma unroll
            for (int q = 0; q < 4; q++) {
                float4 a = pm[q]; float4 c = pn[q];
                rmx[q*4+0] = a.x; rmx[q*4+1] = a.y; rmx[q*4+2] = a.z; rmx[q*4+3] = a.w;
                rmn[q*4+0] = c.x; rmn[q*4+1] = c.y; rmn[q*4+2] = c.z; rmn[q*4+3] = c.w;
            }
            int wo = (dy+1)*3 + (dx+1);
#pragma unroll
            for (int kz = 0; kz < 3; kz++) {
                float wm = ws_s[kz*9 + wo];        // ic=0 (max)
                float wn = ws_s[27 + kz*9 + wo];   // ic=1 (mean)
#pragma unroll
                for (int d = 0; d < 16; d++) {
                    int s = d + kz - 1;
                    if (s >= 0 && s < 16) acc[d] += wm*rmx[s] + wn*rmn[s];
                }
            }
        }
    }
    float* gp = g_gate + pt*128 + (o << 4);
#pragma unroll
    for (int q = 0; q < 4; q++)
        *(float4*)(gp + q*4) = make_float4(acc[q*4+0], acc[q*4+1], acc[q*4+2], acc[q*4+3]);

    float s1 = 0.f, s2 = 0.f;
#pragma unroll
    for (int d = 0; d < 16; d++) { s1 += acc[d]; s2 += acc[d]*acc[d]; }
    // reduce over the 4 pts in this warp sharing each o (lanes differ by 8/16)
    s1 += __shfl_xor_sync(0xffffffffu, s1, 8);
    s2 += __shfl_xor_sync(0xffffffffu, s2, 8);
    s1 += __shfl_xor_sync(0xffffffffu, s1, 16);
    s2 += __shfl_xor_sync(0xffffffffu, s2, 16);
    if ((tid & 31) < 8) { atomicAdd(&bsum[o], s1); atomicAdd(&bss[o], s2); }
    __syncthreads();
    if (tid < 8) {
        g_psumArr[blockIdx.x*8 + tid] = bsum[tid];
        g_pssArr [blockIdx.x*8 + tid] = bss[tid];
    }
}

// ---------------- kernel 3b: BN stats finalize ---------------------------
__global__ void k_bnstats() {
    __shared__ float ss1[256], ss2[256];
    int tid = threadIdx.x;
    int o = tid & 7, seg = tid >> 3;
    float a = 0.f, c = 0.f;
    for (int i = seg*32; i < seg*32 + 32; i++) {
        a += g_psumArr[i*8 + o];
        c += g_pssArr [i*8 + o];
    }
    ss1[tid] = a; ss2[tid] = c;
    __syncthreads();
    if (tid < 8) {
        float A = 0.f, C = 0.f;
        for (int s = 0; s < 32; s++) { A += ss1[s*8 + tid]; C += ss2[s*8 + tid]; }
        const float inv = 1.f / 524288.f;   // B*D*h*w
        float mu = A * inv;
        float var = C * inv - mu*mu;
        g_bnMu[tid]   = mu;
        g_bnRstd[tid] = rsqrtf(var + EPSV);
    }
}

// ---------------- kernel 4: gate apply + LayerNorm + transpose out -------
// one block per (o,b); smem-stages caps_next so reads are d-fast coalesced
// and writes are yx-fast coalesced.
#define SM4_STRIDE 1025   // conflict-free transpose stride
__global__ __launch_bounds__(256) void k_final(const float* __restrict__ bn_gamma,
                                               const float* __restrict__ bn_beta,
                                               const float* __restrict__ ln_gamma,
                                               const float* __restrict__ ln_beta,
                                               float* __restrict__ out) {
    extern __shared__ float sm4[];   // 16*1025 data + 32 scratch
    const int RED = 16*SM4_STRIDE;
    int tid = threadIdx.x;
    int b = blockIdx.x & 31;
    int o = blockIdx.x >> 5;
    float mu = g_bnMu[o], rstd = g_bnRstd[o];
    float gam = bn_gamma[0], bet = bn_beta[0];

    int d   = tid & 15;
    int yxb = tid >> 4;
    const float* gp = g_gate   + (b << 10)*128 + (o << 4) + d;
    const float* sp = g_sumAtt + (b << 10)*128 + (o << 4) + d;
    float s = 0.f, ss = 0.f;
    for (int i = 0; i < 64; i++) {
        int yx = yxb + i*16;
        float gg = gp[yx*128];
        float sa = sp[yx*128];
        float z  = (gg - mu) * rstd * gam + bet;
        float sc = 1.f / (1.f + expf(-z));
        float cn = (1.f + sc) * sa;
        sm4[d*SM4_STRIDE + yx] = cn;
        s += cn; ss += cn*cn;
    }
    // block reduction for LN stats
#pragma unroll
    for (int off = 16; off >= 1; off >>= 1) {
        s  += __shfl_xor_sync(0xffffffffu, s,  off);
        ss += __shfl_xor_sync(0xffffffffu, ss, off);
    }
    int wid = tid >> 5;
    if ((tid & 31) == 0) { sm4[RED + wid] = s; sm4[RED + 8 + wid] = ss; }
    __syncthreads();
    if (tid == 0) {
        float S = 0.f, Q = 0.f;
        for (int w = 0; w < 8; w++) { S += sm4[RED + w]; Q += sm4[RED + 8 + w]; }
        const float inv = 1.f / 16384.f;
        float m = S * inv;
        float var = Q * inv - m*m;
        sm4[RED + 16] = m;
        sm4[RED + 17] = rsqrtf(var + EPSV);
    }
    __syncthreads();
    float m = sm4[RED + 16], r = sm4[RED + 17];
    float* ob = out + ((o*32 + b) << 14);   // [Cout][B][D][S][S]
    for (int i = 0; i < 64; i++) {
        int idx = i*256 + tid;              // idx = d*1024 + yx
        float v = sm4[(idx >> 10)*SM4_STRIDE + (idx & 1023)];
        ob[idx] = (v - m) * r * ln_gamma[idx] + ln_beta[idx];
    }
}

// ---------------- launch ------------------------------------------------
extern "C" void kernel_launch(void* const* d_in, const int* in_sizes, int n_in,
                              void* d_out, int out_size) {
    const float* caps = (const float*)d_in[0];
    const float* Wt   = (const float*)d_in[1];
    const float* bt   = (const float*)d_in[2];
    const float* Wv   = (const float*)d_in[3];
    const float* bv   = (const float*)d_in[4];
    const float* Ws   = (const float*)d_in[5];
    const float* bng  = (const float*)d_in[6];
    const float* bnb  = (const float*)d_in[7];
    const float* lng  = (const float*)d_in[8];
    const float* lnb  = (const float*)d_in[9];
    float* out = (float*)d_out;

    k_transpose<<<576, 256>>>(Wt);
    dim3 gconv(8, 256);
    k_conv<<<gconv, 256>>>(caps, bt);
    k_route<<<NPTS/8, 256>>>(Wv, bv);
    k_gate<<<NPTS/32, 256>>>(Ws);
    k_bnstats<<<1, 256>>>();
    static const int smem4 = (16*SM4_STRIDE + 32) * 4;
    cudaFuncSetAttribute(k_final, cudaFuncAttributeMaxDynamicSharedMemorySize, smem4);
    k_final<<<256, 256, smem4>>>(bng, bnb, lng, lnb, out);
}

// round 2
// speedup vs baseline: 1.0759x; 1.0759x over previous
#include <cuda_runtime.h>
#include <math.h>

// Problem constants
#define BATCH 32
#define CIN   8
#define COUT  8
#define KP    4
#define DIN   16
#define DOUT  16
#define SS_   32
#define EPSV  1e-5f

#define NPTS  (BATCH*SS_*SS_)      // 32768 spatial points (b,y,x)
#define NOC   (CIN*COUT*DOUT)      // 1024 conv output channels
#define KDIM  (DIN*9)              // 144 GEMM K
#define OD    (COUT*DOUT)          // 128 (o,d) pairs per point

typedef unsigned long long u64;

// ---------------- packed f32x2 helpers (sm_100+ PTX) ---------------------
__device__ __forceinline__ u64 pack2(float lo, float hi) {
    u64 d; asm("mov.b64 %0,{%1,%2};" : "=l"(d) : "f"(lo), "f"(hi)); return d;
}
__device__ __forceinline__ u64 ffma2(u64 a, u64 b, u64 c) {
    u64 d; asm("fma.rn.f32x2 %0,%1,%2,%3;" : "=l"(d) : "l"(a), "l"(b), "l"(c)); return d;
}
__device__ __forceinline__ u64 fadd2(u64 a, u64 b) {
    u64 d; asm("add.rn.f32x2 %0,%1,%2;" : "=l"(d) : "l"(a), "l"(b)); return d;
}
__device__ __forceinline__ void unpack2(u64 d, float& lo, float& hi) {
    asm("mov.b64 {%0,%1},%2;" : "=f"(lo), "=f"(hi) : "l"(d));
}

// ---------------- scratch (device globals; no allocations allowed) -------
__device__ __align__(128) float g_Wk[KDIM*NOC];              // transposed conv weights [k][oc]
__device__ __align__(128) float g_votes[NPTS*NOC];           // conv output, channel-last [pt][oc]
__device__ __align__(128) float g_sumAtt[NPTS*OD];
__device__ __align__(128) float g_pmax[NPTS*OD];
__device__ __align__(128) float g_pmean[NPTS*OD];
__device__ __align__(128) float g_gate[NPTS*OD];
__device__ float g_psumArr[1024*8];
__device__ float g_pssArr[1024*8];
__device__ float g_bnMu[8];
__device__ float g_bnRstd[8];

// ---------------- kernel 0: transpose Wt [oc][k] -> Wk [k][oc] -----------
__global__ void k_transpose(const float* __restrict__ Wt) {
    int idx = blockIdx.x * 256 + threadIdx.x;
    int k  = idx >> 10;
    int oc = idx & 1023;
    g_Wk[idx] = Wt[oc * KDIM + k];
}

// ---------------- kernel 1: implicit-GEMM conv (3x3, pad1), f32x2 --------
// C[m][n] = sum_k A[m][k]*B[k][n] + bt[n];  m=(b,y,x), n=oc, k=(ci,ky,kx)
// 128x128 tile, 8x8 per thread (packed as 8x4 f32x2), BK=8, 256 threads.
__global__ __launch_bounds__(256) void k_conv(const float* __restrict__ caps,
                                              const float* __restrict__ bt) {
    __shared__ __align__(16) float As[8][128];
    __shared__ __align__(16) float Bs[8][128];
    __shared__ float bts[128];
    const int tid = threadIdx.x;
    const int n0 = blockIdx.x * 128;
    const int m0 = blockIdx.y * 128;
    if (tid < 128) bts[tid] = bt[n0 + tid];
    const int tx = tid & 15, ty = tid >> 4;
    const int k_l = tid >> 5;
    const int mq  = (tid & 31) * 4;

    u64 acc2[8][4];
#pragma unroll
    for (int i = 0; i < 8; i++)
#pragma unroll
        for (int j = 0; j < 4; j++) acc2[i][j] = 0ULL;

    for (int kt = 0; kt < KDIM/8; kt++) {
        __syncthreads();
        // B tile
        float4 bv4 = *(const float4*)(g_Wk + (kt*8 + k_l)*1024 + n0 + mq);
        *(float4*)&Bs[k_l][mq] = bv4;
        // A tile (im2col gather)
        int kg = kt*8 + k_l;
        int ci = kg / 9;
        int r  = kg - ci*9;
        int dy = r/3 - 1;
        int dx = (r - (r/3)*3) - 1;
        const float* cp = caps + ci*1024;
#pragma unroll
        for (int i = 0; i < 4; i++) {
            int m = m0 + mq + i;
            int b = m >> 10, yx = m & 1023;
            int y = yx >> 5, x = yx & 31;
            int yy = y + dy, xx = x + dx;
            float v = 0.f;
            if ((unsigned)yy < 32u && (unsigned)xx < 32u)
                v = cp[b*16384 + yy*32 + xx];
            As[k_l][mq + i] = v;
        }
        __syncthreads();
#pragma unroll
        for (int k = 0; k < 8; k++) {
            float a[8];
            u64 a2[8], b2[4];
            *(float4*)&a[0]  = *(const float4*)&As[k][ty*4];
            *(float4*)&a[4]  = *(const float4*)&As[k][64 + ty*4];
            ulonglong2 t0 = *(const ulonglong2*)&Bs[k][tx*4];
            ulonglong2 t1 = *(const ulonglong2*)&Bs[k][64 + tx*4];
            b2[0] = t0.x; b2[1] = t0.y; b2[2] = t1.x; b2[3] = t1.y;
#pragma unroll
            for (int i = 0; i < 8; i++) a2[i] = pack2(a[i], a[i]);
#pragma unroll
            for (int i = 0; i < 8; i++)
#pragma unroll
                for (int j = 0; j < 4; j++)
                    acc2[i][j] = ffma2(a2[i], b2[j], acc2[i][j]);
        }
    }
    // epilogue: + bias, store channel-last votes
#pragma unroll
    for (int i = 0; i < 8; i++) {
        int row = (i < 4) ? (ty*4 + i) : (64 + ty*4 + i - 4);
        float* outp = g_votes + (m0 + row)*1024 + n0;
#pragma unroll
        for (int jh = 0; jh < 2; jh++) {
            int cb = jh*64 + tx*4;
            float c0, c1, c2, c3;
            unpack2(acc2[i][jh*2+0], c0, c1);
            unpack2(acc2[i][jh*2+1], c2, c3);
            float4 o4;
            o4.x = c0 + bts[cb+0];
            o4.y = c1 + bts[cb+1];
            o4.z = c2 + bts[cb+2];
            o4.w = c3 + bts[cb+3];
            *(float4*)(outp + cb) = o4;
        }
    }
}

// ---------------- kernel 2: values + pooling + agreement routing (f32x2) -
__global__ __launch_bounds__(256) void k_route(const float* __restrict__ Wv,
                                               const float* __restrict__ bv) {
    __shared__ __align__(16) float wv_s[2048];
    __shared__ float bv_s[256];
    int tid = threadIdx.x;
    for (int i = tid; i < 2048; i += 256) wv_s[i] = Wv[i];
    if (tid < 256) bv_s[tid] = bv[tid];
    __syncthreads();

    int pt   = blockIdx.x * 8 + (tid >> 5);
    int lane = tid & 31;
    int o    = lane >> 2;
    const float* vp = g_votes + pt * 1024;

    u64 vt2[8][2];
#pragma unroll
    for (int c = 0; c < 8; c++) {
        ulonglong2 t = *(const ulonglong2*)(vp + c*128 + lane*4);
        vt2[c][0] = t.x; vt2[c][1] = t.y;
    }

    u64 ksum2[8][2], kss2[8][2], psum2[2];
    float pmax[4];
#pragma unroll
    for (int c = 0; c < 8; c++) {
        ksum2[c][0] = 0ULL; ksum2[c][1] = 0ULL;
        kss2[c][0]  = 0ULL; kss2[c][1]  = 0ULL;
    }
    psum2[0] = 0ULL; psum2[1] = 0ULL;
#pragma unroll
    for (int j = 0; j < 4; j++) pmax[j] = -1e30f;

    const float4* wv4 = (const float4*)wv_s;
#pragma unroll
    for (int m = 0; m < 32; m++) {
        float4 wa = wv4[(o*32 + m)*2 + 0];
        float4 wb = wv4[(o*32 + m)*2 + 1];
        float bvv = bv_s[o*32 + m];
        u64 bb = pack2(bvv, bvv);
        u64 v0 = bb, v1 = bb, w;
        w = pack2(wa.x, wa.x); v0 = ffma2(w, vt2[0][0], v0); v1 = ffma2(w, vt2[0][1], v1);
        w = pack2(wa.y, wa.y); v0 = ffma2(w, vt2[1][0], v0); v1 = ffma2(w, vt2[1][1], v1);
        w = pack2(wa.z, wa.z); v0 = ffma2(w, vt2[2][0], v0); v1 = ffma2(w, vt2[2][1], v1);
        w = pack2(wa.w, wa.w); v0 = ffma2(w, vt2[3][0], v0); v1 = ffma2(w, vt2[3][1], v1);
        w = pack2(wb.x, wb.x); v0 = ffma2(w, vt2[4][0], v0); v1 = ffma2(w, vt2[4][1], v1);
        w = pack2(wb.y, wb.y); v0 = ffma2(w, vt2[5][0], v0); v1 = ffma2(w, vt2[5][1], v1);
        w = pack2(wb.z, wb.z); v0 = ffma2(w, vt2[6][0], v0); v1 = ffma2(w, vt2[6][1], v1);
        w = pack2(wb.w, wb.w); v0 = ffma2(w, vt2[7][0], v0); v1 = ffma2(w, vt2[7][1], v1);
        const int c2 = m & 7;
        ksum2[c2][0] = fadd2(ksum2[c2][0], v0);
        ksum2[c2][1] = fadd2(ksum2[c2][1], v1);
        kss2[c2][0]  = ffma2(v0, v0, kss2[c2][0]);
        kss2[c2][1]  = ffma2(v1, v1, kss2[c2][1]);
        psum2[0]     = fadd2(psum2[0], v0);
        psum2[1]     = fadd2(psum2[1], v1);
        float f0, f1, f2, f3;
        unpack2(v0, f0, f1); unpack2(v1, f2, f3);
        pmax[0] = fmaxf(pmax[0], f0);
        pmax[1] = fmaxf(pmax[1], f1);
        pmax[2] = fmaxf(pmax[2], f2);
        pmax[3] = fmaxf(pmax[3], f3);
    }

    float sA[4], pM[4], pMe[4];
#pragma unroll
    for (int p = 0; p < 2; p++) {
        float ks[8][2], kq[8][2], ps[2];
#pragma unroll
        for (int c2 = 0; c2 < 8; c2++) {
            unpack2(ksum2[c2][p], ks[c2][0], ks[c2][1]);
            unpack2(kss2[c2][p],  kq[c2][0], kq[c2][1]);
        }
        unpack2(psum2[p], ps[0], ps[1]);
#pragma unroll
        for (int h = 0; h < 2; h++) {
            int j = p*2 + h;
            float mean_c[8], std_c[8];
            float mn = 1e30f;
#pragma unroll
            for (int c2 = 0; c2 < 8; c2++) {
                float mu  = ks[c2][h] * 0.25f;
                float var = fmaxf(kq[c2][h] * 0.25f - mu*mu, 0.f);
                float sd  = sqrtf(var);
                mean_c[c2] = mu; std_c[c2] = sd;
                mn = fminf(mn, sd);
            }
            float wsum = 0.f, av = 0.f;
#pragma unroll
            for (int c2 = 0; c2 < 8; c2++) {
                float wq = (std_c[c2] > 0.f) ? (mn / std_c[c2]) : 1.0f;
                wsum += wq;
                av   += wq * mean_c[c2];
            }
            sA[j]  = av / wsum;
            pM[j]  = pmax[j];
            pMe[j] = ps[h] * (1.f/32.f);
        }
    }
    int off = pt*128 + lane*4;
    *(float4*)(g_sumAtt + off) = make_float4(sA[0], sA[1], sA[2], sA[3]);
    *(float4*)(g_pmax   + off) = make_float4(pM[0], pM[1], pM[2], pM[3]);
    *(float4*)(g_pmean  + off) = make_float4(pMe[0], pMe[1], pMe[2], pMe[3]);
}

// ---------------- kernel 3: 3D gate conv (3x3x3, pad1) + BN partials -----
__global__ __launch_bounds__(256) void k_gate(const float* __restrict__ Ws) {
    __shared__ float ws_s[54];
    __shared__ float bsum[8], bss[8];
    int tid = threadIdx.x;
    if (tid < 54) ws_s[tid] = Ws[tid];
    if (tid < 8) { bsum[tid] = 0.f; bss[tid] = 0.f; }
    __syncthreads();

    int pt = blockIdx.x * 32 + (tid >> 3);
    int o  = tid & 7;
    int b  = pt >> 10, yx = pt & 1023;
    int y  = yx >> 5,  x  = yx & 31;

    float acc[16];
#pragma unroll
    for (int d = 0; d < 16; d++) acc[d] = 0.f;

    for (int dy = -1; dy <= 1; dy++) {
        int yy = y + dy;
        if ((unsigned)yy >= 32u) continue;
        for (int dx = -1; dx <= 1; dx++) {
            int xx = x + dx;
            if ((unsigned)xx >= 32u) continue;
            int base = ((b << 10) + (yy << 5) + xx)*128 + (o << 4);
            const float4* pm = (const float4*)(g_pmax  + base);
            const float4* pn = (const float4*)(g_pmean + base);
            float rmx[16], rmn[16];
#pragma unroll
            for (int q = 0; q < 4; q++) {
                float4 a = pm[q]; float4 c = pn[q];
                rmx[q*4+0] = a.x; rmx[q*4+1] = a.y; rmx[q*4+2] = a.z; rmx[q*4+3] = a.w;
                rmn[q*4+0] = c.x; rmn[q*4+1] = c.y; rmn[q*4+2] = c.z; rmn[q*4+3] = c.w;
            }
            int wo = (dy+1)*3 + (dx+1);
#pragma unroll
            for (int kz = 0; kz < 3; kz++) {
                float wm = ws_s[kz*9 + wo];
                float wn = ws_s[27 + kz*9 + wo];
#pragma unroll
                for (int d = 0; d < 16; d++) {
                    int s = d + kz - 1;
                    if (s >= 0 && s < 16) acc[d] += wm*rmx[s] + wn*rmn[s];
                }
            }
        }
    }
    float* gp = g_gate + pt*128 + (o << 4);
#pragma unroll
    for (int q = 0; q < 4; q++)
        *(float4*)(gp + q*4) = make_float4(acc[q*4+0], acc[q*4+1], acc[q*4+2], acc[q*4+3]);

    float s1 = 0.f, s2 = 0.f;
#pragma unroll
    for (int d = 0; d < 16; d++) { s1 += acc[d]; s2 += acc[d]*acc[d]; }
    s1 += __shfl_xor_sync(0xffffffffu, s1, 8);
    s2 += __shfl_xor_sync(0xffffffffu, s2, 8);
    s1 += __shfl_xor_sync(0xffffffffu, s1, 16);
    s2 += __shfl_xor_sync(0xffffffffu, s2, 16);
    if ((tid & 31) < 8) { atomicAdd(&bsum[o], s1); atomicAdd(&bss[o], s2); }
    __syncthreads();
    if (tid < 8) {
        g_psumArr[blockIdx.x*8 + tid] = bsum[tid];
        g_pssArr [blockIdx.x*8 + tid] = bss[tid];
    }
}

// ---------------- kernel 3b: BN stats finalize ---------------------------
__global__ void k_bnstats() {
    __shared__ float ss1[256], ss2[256];
    int tid = threadIdx.x;
    int o = tid & 7, seg = tid >> 3;
    float a = 0.f, c = 0.f;
    for (int i = seg*32; i < seg*32 + 32; i++) {
        a += g_psumArr[i*8 + o];
        c += g_pssArr [i*8 + o];
    }
    ss1[tid] = a; ss2[tid] = c;
    __syncthreads();
    if (tid < 8) {
        float A = 0.f, C = 0.f;
        for (int s = 0; s < 32; s++) { A += ss1[s*8 + tid]; C += ss2[s*8 + tid]; }
        const float inv = 1.f / 524288.f;
        float mu = A * inv;
        float var = C * inv - mu*mu;
        g_bnMu[tid]   = mu;
        g_bnRstd[tid] = rsqrtf(var + EPSV);
    }
}

// ---------------- kernel 4: gate apply + LayerNorm + transpose out -------
#define SM4_STRIDE 1025
__global__ __launch_bounds__(256) void k_final(const float* __restrict__ bn_gamma,
                                               const float* __restrict__ bn_beta,
                                               const float* __restrict__ ln_gamma,
                                               const float* __restrict__ ln_beta,
                                               float* __restrict__ out) {
    extern __shared__ float sm4[];
    const int RED = 16*SM4_STRIDE;
    int tid = threadIdx.x;
    int b = blockIdx.x & 31;
    int o = blockIdx.x >> 5;
    float mu = g_bnMu[o], rstd = g_bnRstd[o];
    float gam = bn_gamma[0], bet = bn_beta[0];

    int d   = tid & 15;
    int yxb = tid >> 4;
    const float* gp = g_gate   + (b << 10)*128 + (o << 4) + d;
    const float* sp = g_sumAtt + (b << 10)*128 + (o << 4) + d;
    float s = 0.f, ss = 0.f;
    for (int i = 0; i < 64; i++) {
        int yx = yxb + i*16;
        float gg = gp[yx*128];
        float sa = sp[yx*128];
        float z  = (gg - mu) * rstd * gam + bet;
        float sc = 1.f / (1.f + expf(-z));
        float cn = (1.f + sc) * sa;
        sm4[d*SM4_STRIDE + yx] = cn;
        s += cn; ss += cn*cn;
    }
#pragma unroll
    for (int off = 16; off >= 1; off >>= 1) {
        s  += __shfl_xor_sync(0xffffffffu, s,  off);
        ss += __shfl_xor_sync(0xffffffffu, ss, off);
    }
    int wid = tid >> 5;
    if ((tid & 31) == 0) { sm4[RED + wid] = s; sm4[RED + 8 + wid] = ss; }
    __syncthreads();
    if (tid == 0) {
        float S = 0.f, Q = 0.f;
        for (int w = 0; w < 8; w++) { S += sm4[RED + w]; Q += sm4[RED + 8 + w]; }
        const float inv = 1.f / 16384.f;
        float m = S * inv;
        float var = Q * inv - m*m;
        sm4[RED + 16] = m;
        sm4[RED + 17] = rsqrtf(var + EPSV);
    }
    __syncthreads();
    float m = sm4[RED + 16], r = sm4[RED + 17];
    float* ob = out + ((o*32 + b) << 14);
    for (int i = 0; i < 64; i++) {
        int idx = i*256 + tid;
        float v = sm4[(idx >> 10)*SM4_STRIDE + (idx & 1023)];
        ob[idx] = (v - m) * r * ln_gamma[idx] + ln_beta[idx];
    }
}

// ---------------- launch ------------------------------------------------
extern "C" void kernel_launch(void* const* d_in, const int* in_sizes, int n_in,
                              void* d_out, int out_size) {
    const float* caps = (const float*)d_in[0];
    const float* Wt   = (const float*)d_in[1];
    const float* bt   = (const float*)d_in[2];
    const float* Wv   = (const float*)d_in[3];
    const float* bv   = (const float*)d_in[4];
    const float* Ws   = (const float*)d_in[5];
    const float* bng  = (const float*)d_in[6];
    const float* bnb  = (const float*)d_in[7];
    const float* lng  = (const float*)d_in[8];
    const float* lnb  = (const float*)d_in[9];
    float* out = (float*)d_out;

    k_transpose<<<576, 256>>>(Wt);
    dim3 gconv(8, 256);
    k_conv<<<gconv, 256>>>(caps, bt);
    k_route<<<NPTS/8, 256>>>(Wv, bv);
    k_gate<<<NPTS/32, 256>>>(Ws);
    k_bnstats<<<1, 256>>>();
    static const int smem4 = (16*SM4_STRIDE + 32) * 4;
    cudaFuncSetAttribute(k_final, cudaFuncAttributeMaxDynamicSharedMemorySize, smem4);
    k_final<<<256, 256, smem4>>>(bng, bnb, lng, lnb, out);
}

// round 4
// speedup vs baseline: 1.2864x; 1.1957x over previous
#include <cuda_runtime.h>
#include <cuda_bf16.h>
#include <math.h>
#include <stdint.h>
#include <string.h>

// Problem constants
#define BATCH 32
#define CIN   8
#define COUT  8
#define KP    4
#define DIN   16
#define DOUT  16
#define SS_   32
#define EPSV  1e-5f

#define NPTS  (BATCH*SS_*SS_)      // 32768 spatial points (b,y,x)
#define NOC   (CIN*COUT*DOUT)      // 1024 conv output channels
#define KDIM  (DIN*9)              // 144 GEMM K (fp32)
#define KEFF  432                  // 3*144 split-bf16 K
#define KPAD  448                  // padded: 14 stages of BK=32
#define OD    (COUT*DOUT)          // 128 (o,d) pairs per point

typedef unsigned long long u64;

// ---------------- packed f32x2 helpers ------------------------------------
__device__ __forceinline__ u64 pack2(float lo, float hi) {
    u64 d; asm("mov.b64 %0,{%1,%2};" : "=l"(d) : "f"(lo), "f"(hi)); return d;
}
__device__ __forceinline__ u64 ffma2(u64 a, u64 b, u64 c) {
    u64 d; asm("fma.rn.f32x2 %0,%1,%2,%3;" : "=l"(d) : "l"(a), "l"(b), "l"(c)); return d;
}
__device__ __forceinline__ u64 fadd2(u64 a, u64 b) {
    u64 d; asm("add.rn.f32x2 %0,%1,%2;" : "=l"(d) : "l"(a), "l"(b)); return d;
}
__device__ __forceinline__ void unpack2(u64 d, float& lo, float& hi) {
    asm("mov.b64 {%0,%1},%2;" : "=f"(lo), "=f"(hi) : "l"(d));
}

__device__ __forceinline__ uint32_t smem_u32(const void* p) {
    uint32_t a;
    asm("{ .reg .u64 t; cvta.to.shared.u64 t, %1; cvt.u32.u64 %0, t; }" : "=r"(a) : "l"(p));
    return a;
}
#define CP_ASYNC16(dst, src) asm volatile("cp.async.cg.shared.global [%0], [%1], 16;" :: "r"(dst), "l"(src))
#define CP_COMMIT()          asm volatile("cp.async.commit_group;" ::: "memory")

// ---------------- scratch (device globals) --------------------------------
__device__ __align__(128) __nv_bfloat16 g_Ab[NPTS*KPAD];   // split-bf16 im2col A [p][e]
__device__ __align__(128) __nv_bfloat16 g_Bb[NOC*KPAD];    // split-bf16 weights [oc][e]
__device__ __align__(128) float g_votes[NPTS*NOC];         // conv output [pt][oc]
__device__ __align__(128) float g_sumAtt[NPTS*OD];
__device__ __align__(128) float g_pmax[NPTS*OD];
__device__ __align__(128) float g_pmean[NPTS*OD];
__device__ __align__(128) float g_gate[NPTS*OD];
__device__ float g_psumArr[1024*8];
__device__ float g_pssArr[1024*8];
__device__ float g_bnMu[8];
__device__ float g_bnRstd[8];

// ---------------- kernel: prep B (split Wt -> bf16 [oc][448]) -------------
// A terms: [hi, hi, lo]; B terms: [hi, lo, hi]  => hi*hi + hi*lo + lo*hi
__global__ void k_prepB(const float* __restrict__ Wt) {
    int idx = blockIdx.x * 256 + threadIdx.x;   // 1792 blocks exact
    int oc = idx / KPAD, e = idx % KPAD;
    float v = 0.f;
    if (e < KEFF) {
        int t = e / KDIM, k = e - t*KDIM;
        float w = Wt[oc*KDIM + k];
        float hi = __bfloat162float(__float2bfloat16_rn(w));
        v = (t == 1) ? (w - hi) : hi;
    }
    g_Bb[idx] = __float2bfloat16_rn(v);
}

// ---------------- kernel: prep A (im2col + split -> bf16 [p][448]) --------
// block = 64 points (2 y-rows of one image). grid 512.
__global__ __launch_bounds__(256) void k_prepA(const float* __restrict__ caps) {
    extern __shared__ char sm[];
    float* raw = (float*)sm;                       // 16 din x 4 rows x 32 = 2048 f
    uint32_t* outp = (uint32_t*)(sm + 8192);       // [64][225] u32 (padded stride)
    int tid = threadIdx.x;
    int m064 = blockIdx.x * 64;
    int b = m064 >> 10;
    int y0 = (m064 & 1023) >> 5;
    for (int i = tid; i < 2048; i += 256) {
        int din = i >> 7, rem = i & 127, yy = y0 - 1 + (rem >> 5), x = rem & 31;
        raw[i] = ((unsigned)yy < 32u) ? caps[b*16384 + din*1024 + yy*32 + x] : 0.f;
    }
    __syncthreads();
    int p = tid & 63, part = tid >> 6;
    int y_local = p >> 5, x = p & 31;
    bool isLo = part >= 2;
    int j0 = (part & 1) * 36;
    for (int j = j0; j < j0 + 36; j++) {
        float v[2];
#pragma unroll
        for (int q = 0; q < 2; q++) {
            int k = 2*j + q;
            int din = k / 9, r = k - din*9;
            int ry = r / 3;
            int xx = x + (r - ry*3) - 1;
            v[q] = ((unsigned)xx < 32u) ? raw[din*128 + (y_local + ry)*32 + xx] : 0.f;
        }
        uint32_t u;
        if (!isLo) {
            __nv_bfloat162 h2 = __float22bfloat162_rn(make_float2(v[0], v[1]));
            memcpy(&u, &h2, 4);
            outp[p*225 + j] = u;          // t=0 (hi)
            outp[p*225 + 72 + j] = u;     // t=1 (hi dup)
        } else {
            float h0 = __bfloat162float(__float2bfloat16_rn(v[0]));
            float h1 = __bfloat162float(__float2bfloat16_rn(v[1]));
            __nv_bfloat162 l2 = __float22bfloat162_rn(make_float2(v[0]-h0, v[1]-h1));
            memcpy(&u, &l2, 4);
            outp[p*225 + 144 + j] = u;    // t=2 (lo)
        }
    }
    if (part == 3) {
#pragma unroll
        for (int jz = 216; jz < 224; jz++) outp[p*225 + jz] = 0;  // K pad
    }
    __syncthreads();
    uint32_t* gdst = (uint32_t*)((char*)g_Ab + (size_t)m064 * (KPAD*2));
    for (int i = tid; i < 64*224; i += 256)
        gdst[i] = outp[(i/224)*225 + (i%224)];
}

// ---------------- kernel: bf16 mma.sync GEMM votes = A x B^T + bias -------
// 128x128 block tile, BK=32, double-buffered cp.async, 8 warps (2M x 4N),
// warp tile 64x32 via m16n8k16. smem stride 40 bf16 (conflict-free frags).
#define SA_STR 40
__device__ __forceinline__ void load_tile(uint32_t sA, uint32_t sB,
                                          const char* Asrc, const char* Bsrc,
                                          int kstage, int tid) {
#pragma unroll
    for (int i = 0; i < 2; i++) {
        int q = i*256 + tid;
        int row = q >> 2, kc = q & 3;
        CP_ASYNC16(sA + row*(SA_STR*2) + kc*16,
                   Asrc + (size_t)row*(KPAD*2) + kstage*64 + kc*16);
    }
#pragma unroll
    for (int i = 0; i < 2; i++) {
        int q = i*256 + tid;
        int row = q >> 2, kc = q & 3;
        CP_ASYNC16(sB + row*(SA_STR*2) + kc*16,
                   Bsrc + (size_t)row*(KPAD*2) + kstage*64 + kc*16);
    }
}

__global__ __launch_bounds__(256) void k_gemm(const float* __restrict__ bt) {
    __shared__ __align__(16) __nv_bfloat16 As[2][128*SA_STR];
    __shared__ __align__(16) __nv_bfloat16 Bs[2][128*SA_STR];
    __shared__ float bias_s[128];
    const int tid = threadIdx.x;
    const int lane = tid & 31;
    const int wid = tid >> 5;
    const int warpM = wid & 1;     // 2 M-warps
    const int warpN = wid >> 1;    // 4 N-warps
    const int n0 = blockIdx.x * 128;
    const int m0 = blockIdx.y * 128;
    if (tid < 128) bias_s[tid] = bt[n0 + tid];

    const char* Asrc = (const char*)g_Ab + (size_t)m0 * (KPAD*2);
    const char* Bsrc = (const char*)g_Bb + (size_t)n0 * (KPAD*2);
    const uint32_t sA0 = smem_u32(&As[0][0]), sA1 = smem_u32(&As[1][0]);
    const uint32_t sB0 = smem_u32(&Bs[0][0]), sB1 = smem_u32(&Bs[1][0]);

    load_tile(sA0, sB0, Asrc, Bsrc, 0, tid); CP_COMMIT();
    load_tile(sA1, sB1, Asrc, Bsrc, 1, tid); CP_COMMIT();

    float acc[4][4][4];
#pragma unroll
    for (int a = 0; a < 4; a++)
#pragma unroll
        for (int b = 0; b < 4; b++)
#pragma unroll
            for (int c = 0; c < 4; c++) acc[a][b][c] = 0.f;

    const int qr = lane >> 2;   // 0..7
    const int qc = lane & 3;    // 0..3

    for (int s = 0; s < 14; s++) {
        if (s == 13) asm volatile("cp.async.wait_group 0;" ::: "memory");
        else         asm volatile("cp.async.wait_group 1;" ::: "memory");
        __syncthreads();
        const __nv_bfloat16* Ab = As[s & 1];
        const __nv_bfloat16* Bb = Bs[s & 1];
#pragma unroll
        for (int kk = 0; kk < 2; kk++) {
            uint32_t afr[4][4], bfr[4][2];
            const int cbase = kk*16 + qc*2;
#pragma unroll
            for (int mf = 0; mf < 4; mf++) {
                int row = warpM*64 + mf*16 + qr;
                afr[mf][0] = *(const uint32_t*)&Ab[row*SA_STR + cbase];
                afr[mf][1] = *(const uint32_t*)&Ab[(row+8)*SA_STR + cbase];
                afr[mf][2] = *(const uint32_t*)&Ab[row*SA_STR + cbase + 8];
                afr[mf][3] = *(const uint32_t*)&Ab[(row+8)*SA_STR + cbase + 8];
            }
#pragma unroll
            for (int nf = 0; nf < 4; nf++) {
                int nn = warpN*32 + nf*8 + qr;
                bfr[nf][0] = *(const uint32_t*)&Bb[nn*SA_STR + cbase];
                bfr[nf][1] = *(const uint32_t*)&Bb[nn*SA_STR + cbase + 8];
            }
#pragma unroll
            for (int mf = 0; mf < 4; mf++)
#pragma unroll
                for (int nf = 0; nf < 4; nf++) {
                    asm volatile(
                        "mma.sync.aligned.m16n8k16.row.col.f32.bf16.bf16.f32 "
                        "{%0,%1,%2,%3}, {%4,%5,%6,%7}, {%8,%9}, {%0,%1,%2,%3};"
                        : "+f"(acc[mf][nf][0]), "+f"(acc[mf][nf][1]),
                          "+f"(acc[mf][nf][2]), "+f"(acc[mf][nf][3])
                        : "r"(afr[mf][0]), "r"(afr[mf][1]), "r"(afr[mf][2]), "r"(afr[mf][3]),
                          "r"(bfr[nf][0]), "r"(bfr[nf][1]));
                }
        }
        __syncthreads();
        if (s + 2 < 14) {
            if (s & 1) load_tile(sA1, sB1, Asrc, Bsrc, s + 2, tid);
            else       load_tile(sA0, sB0, Asrc, Bsrc, s + 2, tid);
            CP_COMMIT();
        }
    }

    // epilogue: + bias, direct stores
#pragma unroll
    for (int mf = 0; mf < 4; mf++) {
        int row0 = m0 + warpM*64 + mf*16 + qr;
#pragma unroll
        for (int nf = 0; nf < 4; nf++) {
            int cl = warpN*32 + nf*8 + qc*2;
            float b0 = bias_s[cl], b1 = bias_s[cl + 1];
            float2 o0 = make_float2(acc[mf][nf][0] + b0, acc[mf][nf][1] + b1);
            float2 o1 = make_float2(acc[mf][nf][2] + b0, acc[mf][nf][3] + b1);
            *(float2*)(g_votes + (size_t)row0*1024 + n0 + cl) = o0;
            *(float2*)(g_votes + (size_t)(row0+8)*1024 + n0 + cl) = o1;
        }
    }
}

// ---------------- kernel 2: values + pooling + agreement routing (f32x2) -
__global__ __launch_bounds__(256) void k_route(const float* __restrict__ Wv,
                                               const float* __restrict__ bv) {
    __shared__ __align__(16) float wv_s[2048];
    __shared__ float bv_s[256];
    int tid = threadIdx.x;
    for (int i = tid; i < 2048; i += 256) wv_s[i] = Wv[i];
    if (tid < 256) bv_s[tid] = bv[tid];
    __syncthreads();

    int pt   = blockIdx.x * 8 + (tid >> 5);
    int lane = tid & 31;
    int o    = lane >> 2;
    const float* vp = g_votes + pt * 1024;

    u64 vt2[8][2];
#pragma unroll
    for (int c = 0; c < 8; c++) {
        ulonglong2 t = *(const ulonglong2*)(vp + c*128 + lane*4);
        vt2[c][0] = t.x; vt2[c][1] = t.y;
    }

    u64 ksum2[8][2], kss2[8][2], psum2[2];
    float pmax[4];
#pragma unroll
    for (int c = 0; c < 8; c++) {
        ksum2[c][0] = 0ULL; ksum2[c][1] = 0ULL;
        kss2[c][0]  = 0ULL; kss2[c][1]  = 0ULL;
    }
    psum2[0] = 0ULL; psum2[1] = 0ULL;
#pragma unroll
    for (int j = 0; j < 4; j++) pmax[j] = -1e30f;

    const float4* wv4 = (const float4*)wv_s;
#pragma unroll
    for (int m = 0; m < 32; m++) {
        float4 wa = wv4[(o*32 + m)*2 + 0];
        float4 wb = wv4[(o*32 + m)*2 + 1];
        float bvv = bv_s[o*32 + m];
        u64 bb = pack2(bvv, bvv);
        u64 v0 = bb, v1 = bb, w;
        w = pack2(wa.x, wa.x); v0 = ffma2(w, vt2[0][0], v0); v1 = ffma2(w, vt2[0][1], v1);
        w = pack2(wa.y, wa.y); v0 = ffma2(w, vt2[1][0], v0); v1 = ffma2(w, vt2[1][1], v1);
        w = pack2(wa.z, wa.z); v0 = ffma2(w, vt2[2][0], v0); v1 = ffma2(w, vt2[2][1], v1);
        w = pack2(wa.w, wa.w); v0 = ffma2(w, vt2[3][0], v0); v1 = ffma2(w, vt2[3][1], v1);
        w = pack2(wb.x, wb.x); v0 = ffma2(w, vt2[4][0], v0); v1 = ffma2(w, vt2[4][1], v1);
        w = pack2(wb.y, wb.y); v0 = ffma2(w, vt2[5][0], v0); v1 = ffma2(w, vt2[5][1], v1);
        w = pack2(wb.z, wb.z); v0 = ffma2(w, vt2[6][0], v0); v1 = ffma2(w, vt2[6][1], v1);
        w = pack2(wb.w, wb.w); v0 = ffma2(w, vt2[7][0], v0); v1 = ffma2(w, vt2[7][1], v1);
        const int c2 = m & 7;
        ksum2[c2][0] = fadd2(ksum2[c2][0], v0);
        ksum2[c2][1] = fadd2(ksum2[c2][1], v1);
        kss2[c2][0]  = ffma2(v0, v0, kss2[c2][0]);
        kss2[c2][1]  = ffma2(v1, v1, kss2[c2][1]);
        psum2[0]     = fadd2(psum2[0], v0);
        psum2[1]     = fadd2(psum2[1], v1);
        float f0, f1, f2, f3;
        unpack2(v0, f0, f1); unpack2(v1, f2, f3);
        pmax[0] = fmaxf(pmax[0], f0);
        pmax[1] = fmaxf(pmax[1], f1);
        pmax[2] = fmaxf(pmax[2], f2);
        pmax[3] = fmaxf(pmax[3], f3);
    }

    float sA[4], pM[4], pMe[4];
#pragma unroll
    for (int p = 0; p < 2; p++) {
        float ks[8][2], kq[8][2], ps[2];
#pragma unroll
        for (int c2 = 0; c2 < 8; c2++) {
            unpack2(ksum2[c2][p], ks[c2][0], ks[c2][1]);
            unpack2(kss2[c2][p],  kq[c2][0], kq[c2][1]);
        }
        unpack2(psum2[p], ps[0], ps[1]);
#pragma unroll
        for (int h = 0; h < 2; h++) {
            int j = p*2 + h;
            float mean_c[8], std_c[8];
            float mn = 1e30f;
#pragma unroll
            for (int c2 = 0; c2 < 8; c2++) {
                float mu  = ks[c2][h] * 0.25f;
                float var = fmaxf(kq[c2][h] * 0.25f - mu*mu, 0.f);
                float sd  = sqrtf(var);
                mean_c[c2] = mu; std_c[c2] = sd;
                mn = fminf(mn, sd);
            }
            float wsum = 0.f, av = 0.f;
#pragma unroll
            for (int c2 = 0; c2 < 8; c2++) {
                float wq = (std_c[c2] > 0.f) ? (mn / std_c[c2]) : 1.0f;
                wsum += wq;
                av   += wq * mean_c[c2];
            }
            sA[j]  = av / wsum;
            pM[j]  = pmax[j];
            pMe[j] = ps[h] * (1.f/32.f);
        }
    }
    int off = pt*128 + lane*4;
    *(float4*)(g_sumAtt + off) = make_float4(sA[0], sA[1], sA[2], sA[3]);
    *(float4*)(g_pmax   + off) = make_float4(pM[0], pM[1], pM[2], pM[3]);
    *(float4*)(g_pmean  + off) = make_float4(pMe[0], pMe[1], pMe[2], pMe[3]);
}

// ---------------- kernel 3: 3D gate conv (3x3x3, pad1) + BN partials -----
__global__ __launch_bounds__(256) void k_gate(const float* __restrict__ Ws) {
    __shared__ float ws_s[54];
    __shared__ float bsum[8], bss[8];
    int tid = threadIdx.x;
    if (tid < 54) ws_s[tid] = Ws[tid];
    if (tid < 8) { bsum[tid] = 0.f; bss[tid] = 0.f; }
    __syncthreads();

    int pt = blockIdx.x * 32 + (tid >> 3);
    int o  = tid & 7;
    int b  = pt >> 10, yx = pt & 1023;
    int y  = yx >> 5,  x  = yx & 31;

    float acc[16];
#pragma unroll
    for (int d = 0; d < 16; d++) acc[d] = 0.f;

    for (int dy = -1; dy <= 1; dy++) {
        int yy = y + dy;
        if ((unsigned)yy >= 32u) continue;
        for (int dx = -1; dx <= 1; dx++) {
            int xx = x + dx;
            if ((unsigned)xx >= 32u) continue;
            int base = ((b << 10) + (yy << 5) + xx)*128 + (o << 4);
            const float4* pm = (const float4*)(g_pmax  + base);
            const float4* pn = (const float4*)(g_pmean + base);
            float rmx[16], rmn[16];
#pragma unroll
            for (int q = 0; q < 4; q++) {
                float4 a = pm[q]; float4 c = pn[q];
                rmx[q*4+0] = a.x; rmx[q*4+1] = a.y; rmx[q*4+2] = a.z; rmx[q*4+3] = a.w;
                rmn[q*4+0] = c.x; rmn[q*4+1] = c.y; rmn[q*4+2] = c.z; rmn[q*4+3] = c.w;
            }
            int wo = (dy+1)*3 + (dx+1);
#pragma unroll
            for (int kz = 0; kz < 3; kz++) {
                float wm = ws_s[kz*9 + wo];
                float wn = ws_s[27 + kz*9 + wo];
#pragma unroll
                for (int d = 0; d < 16; d++) {
                    int s = d + kz - 1;
                    if (s >= 0 && s < 16) acc[d] += wm*rmx[s] + wn*rmn[s];
                }
            }
        }
    }
    float* gp = g_gate + pt*128 + (o << 4);
#pragma unroll
    for (int q = 0; q < 4; q++)
        *(float4*)(gp + q*4) = make_float4(acc[q*4+0], acc[q*4+1], acc[q*4+2], acc[q*4+3]);

    float s1 = 0.f, s2 = 0.f;
#pragma unroll
    for (int d = 0; d < 16; d++) { s1 += acc[d]; s2 += acc[d]*acc[d]; }
    s1 += __shfl_xor_sync(0xffffffffu, s1, 8);
    s2 += __shfl_xor_sync(0xffffffffu, s2, 8);
    s1 += __shfl_xor_sync(0xffffffffu, s1, 16);
    s2 += __shfl_xor_sync(0xffffffffu, s2, 16);
    if ((tid & 31) < 8) { atomicAdd(&bsum[o], s1); atomicAdd(&bss[o], s2); }
    __syncthreads();
    if (tid < 8) {
        g_psumArr[blockIdx.x*8 + tid] = bsum[tid];
        g_pssArr [blockIdx.x*8 + tid] = bss[tid];
    }
}

// ---------------- kernel 3b: BN stats finalize ---------------------------
__global__ void k_bnstats() {
    __shared__ float ss1[256], ss2[256];
    int tid = threadIdx.x;
    int o = tid & 7, seg = tid >> 3;
    float a = 0.f, c = 0.f;
    for (int i = seg*32; i < seg*32 + 32; i++) {
        a += g_psumArr[i*8 + o];
        c += g_pssArr [i*8 + o];
    }
    ss1[tid] = a; ss2[tid] = c;
    __syncthreads();
    if (tid < 8) {
        float A = 0.f, C = 0.f;
        for (int s = 0; s < 32; s++) { A += ss1[s*8 + tid]; C += ss2[s*8 + tid]; }
        const float inv = 1.f / 524288.f;
        float mu = A * inv;
        float var = C * inv - mu*mu;
        g_bnMu[tid]   = mu;
        g_bnRstd[tid] = rsqrtf(var + EPSV);
    }
}

// ---------------- kernel 4: gate apply + LayerNorm + transpose out -------
#define SM4_STRIDE 1025
__global__ __launch_bounds__(256) void k_final(const float* __restrict__ bn_gamma,
                                               const float* __restrict__ bn_beta,
                                               const float* __restrict__ ln_gamma,
                                               const float* __restrict__ ln_beta,
                                               float* __restrict__ out) {
    extern __shared__ float sm4[];
    const int RED = 16*SM4_STRIDE;
    int tid = threadIdx.x;
    int b = blockIdx.x & 31;
    int o = blockIdx.x >> 5;
    float mu = g_bnMu[o], rstd = g_bnRstd[o];
    float gam = bn_gamma[0], bet = bn_beta[0];

    int d   = tid & 15;
    int yxb = tid >> 4;
    const float* gp = g_gate   + (b << 10)*128 + (o << 4) + d;
    const float* sp = g_sumAtt + (b << 10)*128 + (o << 4) + d;
    float s = 0.f, ss = 0.f;
    for (int i = 0; i < 64; i++) {
        int yx = yxb + i*16;
        float gg = gp[yx*128];
        float sa = sp[yx*128];
        float z  = (gg - mu) * rstd * gam + bet;
        float sc = 1.f / (1.f + expf(-z));
        float cn = (1.f + sc) * sa;
        sm4[d*SM4_STRIDE + yx] = cn;
        s += cn; ss += cn*cn;
    }
#pragma unroll
    for (int off = 16; off >= 1; off >>= 1) {
        s  += __shfl_xor_sync(0xffffffffu, s,  off);
        ss += __shfl_xor_sync(0xffffffffu, ss, off);
    }
    int wid = tid >> 5;
    if ((tid & 31) == 0) { sm4[RED + wid] = s; sm4[RED + 8 + wid] = ss; }
    __syncthreads();
    if (tid == 0) {
        float S = 0.f, Q = 0.f;
        for (int w = 0; w < 8; w++) { S += sm4[RED + w]; Q += sm4[RED + 8 + w]; }
        const float inv = 1.f / 16384.f;
        float m = S * inv;
        float var = Q * inv - m*m;
        sm4[RED + 16] = m;
        sm4[RED + 17] = rsqrtf(var + EPSV);
    }
    __syncthreads();
    float m = sm4[RED + 16], r = sm4[RED + 17];
    float* ob = out + ((o*32 + b) << 14);
    for (int i = 0; i < 64; i++) {
        int idx = i*256 + tid;
        float v = sm4[(idx >> 10)*SM4_STRIDE + (idx & 1023)];
        ob[idx] = (v - m) * r * ln_gamma[idx] + ln_beta[idx];
    }
}

// ---------------- launch ------------------------------------------------
extern "C" void kernel_launch(void* const* d_in, const int* in_sizes, int n_in,
                              void* d_out, int out_size) {
    const float* caps = (const float*)d_in[0];
    const float* Wt   = (const float*)d_in[1];
    const float* bt   = (const float*)d_in[2];
    const float* Wv   = (const float*)d_in[3];
    const float* bv   = (const float*)d_in[4];
    const float* Ws   = (const float*)d_in[5];
    const float* bng  = (const float*)d_in[6];
    const float* bnb  = (const float*)d_in[7];
    const float* lng  = (const float*)d_in[8];
    const float* lnb  = (const float*)d_in[9];
    float* out = (float*)d_out;

    const int smemA = 8192 + 64*225*4;            // 65792
    const int smem4 = (16*SM4_STRIDE + 32) * 4;
    cudaFuncSetAttribute(k_prepA, cudaFuncAttributeMaxDynamicSharedMemorySize, smemA);
    cudaFuncSetAttribute(k_final, cudaFuncAttributeMaxDynamicSharedMemorySize, smem4);

    k_prepB<<<1792, 256>>>(Wt);
    k_prepA<<<512, 256, smemA>>>(caps);
    k_gemm<<<dim3(8, 256), 256>>>(bt);
    k_route<<<NPTS/8, 256>>>(Wv, bv);
    k_gate<<<NPTS/32, 256>>>(Ws);
    k_bnstats<<<1, 256>>>();
    k_final<<<256, 256, smem4>>>(bng, bnb, lng, lnb, out);
}

// round 5
// speedup vs baseline: 1.6531x; 1.2851x over previous
#include <cuda_runtime.h>
#include <cuda_bf16.h>
#include <math.h>
#include <stdint.h>
#include <string.h>

// Problem constants
#define BATCH 32
#define CIN   8
#define COUT  8
#define KP    4
#define DIN   16
#define DOUT  16
#define SS_   32
#define EPSV  1e-5f

#define NPTS  (BATCH*SS_*SS_)      // 32768 spatial points (b,y,x)
#define NOC   (CIN*COUT*DOUT)      // 1024 conv output channels
#define KDIM  (DIN*9)              // 144 GEMM K (fp32)
#define KEFF  432                  // 3*144 split-bf16 K
#define KPAD  448                  // padded: 14 stages of BK=32
#define OD    (COUT*DOUT)          // 128 (o,d) pairs per point

typedef unsigned long long u64;

// ---------------- packed f32x2 helpers ------------------------------------
__device__ __forceinline__ u64 pack2(float lo, float hi) {
    u64 d; asm("mov.b64 %0,{%1,%2};" : "=l"(d) : "f"(lo), "f"(hi)); return d;
}
__device__ __forceinline__ u64 ffma2(u64 a, u64 b, u64 c) {
    u64 d; asm("fma.rn.f32x2 %0,%1,%2,%3;" : "=l"(d) : "l"(a), "l"(b), "l"(c)); return d;
}
__device__ __forceinline__ u64 fadd2(u64 a, u64 b) {
    u64 d; asm("add.rn.f32x2 %0,%1,%2;" : "=l"(d) : "l"(a), "l"(b)); return d;
}
__device__ __forceinline__ void unpack2(u64 d, float& lo, float& hi) {
    asm("mov.b64 {%0,%1},%2;" : "=f"(lo), "=f"(hi) : "l"(d));
}

__device__ __forceinline__ uint32_t smem_u32(const void* p) {
    uint32_t a;
    asm("{ .reg .u64 t; cvta.to.shared.u64 t, %1; cvt.u32.u64 %0, t; }" : "=r"(a) : "l"(p));
    return a;
}
#define CP_ASYNC16(dst, src) asm volatile("cp.async.cg.shared.global [%0], [%1], 16;" :: "r"(dst), "l"(src))
#define CP_COMMIT()          asm volatile("cp.async.commit_group;" ::: "memory")

// ---------------- scratch (device globals) --------------------------------
__device__ __align__(128) __nv_bfloat16 g_Ab[NPTS*KPAD];   // split-bf16 im2col A [p][e]
__device__ __align__(128) __nv_bfloat16 g_Bb[NOC*KPAD];    // split-bf16 weights [oc][e]
__device__ __align__(128) float g_votes[NPTS*NOC];         // conv output [pt][oc]
__device__ __align__(128) float g_sumAtt[NPTS*OD];
__device__ __align__(128) float g_pmax[NPTS*OD];
__device__ __align__(128) float g_pmean[NPTS*OD];
__device__ __align__(128) float g_gate[NPTS*OD];
__device__ float g_psumArr[1024*8];
__device__ float g_pssArr[1024*8];
__device__ float g_bnMu[8];
__device__ float g_bnRstd[8];

// ---------------- kernel: prep B (split Wt -> bf16 [oc][448]) -------------
// A terms: [hi, hi, lo]; B terms: [hi, lo, hi]  => hi*hi + hi*lo + lo*hi
__global__ void k_prepB(const float* __restrict__ Wt) {
    int idx = blockIdx.x * 256 + threadIdx.x;   // 1792 blocks exact
    int oc = idx / KPAD, e = idx % KPAD;
    float v = 0.f;
    if (e < KEFF) {
        int t = e / KDIM, k = e - t*KDIM;
        float w = Wt[oc*KDIM + k];
        float hi = __bfloat162float(__float2bfloat16_rn(w));
        v = (t == 1) ? (w - hi) : hi;
    }
    g_Bb[idx] = __float2bfloat16_rn(v);
}

// ---------------- kernel: prep A (im2col + split -> bf16 [p][448]) --------
// block = 64 points (2 y-rows of one image). grid 512.
__global__ __launch_bounds__(256) void k_prepA(const float* __restrict__ caps) {
    extern __shared__ char sm[];
    float* raw = (float*)sm;                       // 16 din x 4 rows x 32 = 2048 f
    uint32_t* outp = (uint32_t*)(sm + 8192);       // [64][225] u32 (padded stride)
    int tid = threadIdx.x;
    int m064 = blockIdx.x * 64;
    int b = m064 >> 10;
    int y0 = (m064 & 1023) >> 5;
    for (int i = tid; i < 2048; i += 256) {
        int din = i >> 7, rem = i & 127, yy = y0 - 1 + (rem >> 5), x = rem & 31;
        raw[i] = ((unsigned)yy < 32u) ? caps[b*16384 + din*1024 + yy*32 + x] : 0.f;
    }
    __syncthreads();
    int p = tid & 63, part = tid >> 6;
    int y_local = p >> 5, x = p & 31;
    bool isLo = part >= 2;
    int j0 = (part & 1) * 36;
    for (int j = j0; j < j0 + 36; j++) {
        float v[2];
#pragma unroll
        for (int q = 0; q < 2; q++) {
            int k = 2*j + q;
            int din = k / 9, r = k - din*9;
            int ry = r / 3;
            int xx = x + (r - ry*3) - 1;
            v[q] = ((unsigned)xx < 32u) ? raw[din*128 + (y_local + ry)*32 + xx] : 0.f;
        }
        uint32_t u;
        if (!isLo) {
            __nv_bfloat162 h2 = __float22bfloat162_rn(make_float2(v[0], v[1]));
            memcpy(&u, &h2, 4);
            outp[p*225 + j] = u;          // t=0 (hi)
            outp[p*225 + 72 + j] = u;     // t=1 (hi dup)
        } else {
            float h0 = __bfloat162float(__float2bfloat16_rn(v[0]));
            float h1 = __bfloat162float(__float2bfloat16_rn(v[1]));
            __nv_bfloat162 l2 = __float22bfloat162_rn(make_float2(v[0]-h0, v[1]-h1));
            memcpy(&u, &l2, 4);
            outp[p*225 + 144 + j] = u;    // t=2 (lo)
        }
    }
    if (part == 3) {
#pragma unroll
        for (int jz = 216; jz < 224; jz++) outp[p*225 + jz] = 0;  // K pad
    }
    __syncthreads();
    uint32_t* gdst = (uint32_t*)((char*)g_Ab + (size_t)m064 * (KPAD*2));
    for (int i = tid; i < 64*224; i += 256)
        gdst[i] = outp[(i/224)*225 + (i%224)];
}

// ---------------- kernel: bf16 mma.sync GEMM votes = A x B^T + bias -------
// 128x128 block tile, BK=32, double-buffered cp.async, 8 warps (2M x 4N),
// warp tile 64x32 via m16n8k16. smem stride 40 bf16 (conflict-free frags).
#define SA_STR 40
__device__ __forceinline__ void load_tile(uint32_t sA, uint32_t sB,
                                          const char* Asrc, const char* Bsrc,
                                          int kstage, int tid) {
#pragma unroll
    for (int i = 0; i < 2; i++) {
        int q = i*256 + tid;
        int row = q >> 2, kc = q & 3;
        CP_ASYNC16(sA + row*(SA_STR*2) + kc*16,
                   Asrc + (size_t)row*(KPAD*2) + kstage*64 + kc*16);
    }
#pragma unroll
    for (int i = 0; i < 2; i++) {
        int q = i*256 + tid;
        int row = q >> 2, kc = q & 3;
        CP_ASYNC16(sB + row*(SA_STR*2) + kc*16,
                   Bsrc + (size_t)row*(KPAD*2) + kstage*64 + kc*16);
    }
}

__global__ __launch_bounds__(256) void k_gemm(const float* __restrict__ bt) {
    __shared__ __align__(16) __nv_bfloat16 As[2][128*SA_STR];
    __shared__ __align__(16) __nv_bfloat16 Bs[2][128*SA_STR];
    __shared__ float bias_s[128];
    const int tid = threadIdx.x;
    const int lane = tid & 31;
    const int wid = tid >> 5;
    const int warpM = wid & 1;     // 2 M-warps
    const int warpN = wid >> 1;    // 4 N-warps
    const int n0 = blockIdx.x * 128;
    const int m0 = blockIdx.y * 128;
    if (tid < 128) bias_s[tid] = bt[n0 + tid];

    const char* Asrc = (const char*)g_Ab + (size_t)m0 * (KPAD*2);
    const char* Bsrc = (const char*)g_Bb + (size_t)n0 * (KPAD*2);
    const uint32_t sA0 = smem_u32(&As[0][0]), sA1 = smem_u32(&As[1][0]);
    const uint32_t sB0 = smem_u32(&Bs[0][0]), sB1 = smem_u32(&Bs[1][0]);

    load_tile(sA0, sB0, Asrc, Bsrc, 0, tid); CP_COMMIT();
    load_tile(sA1, sB1, Asrc, Bsrc, 1, tid); CP_COMMIT();

    float acc[4][4][4];
#pragma unroll
    for (int a = 0; a < 4; a++)
#pragma unroll
        for (int b = 0; b < 4; b++)
#pragma unroll
            for (int c = 0; c < 4; c++) acc[a][b][c] = 0.f;

    const int qr = lane >> 2;   // 0..7
    const int qc = lane & 3;    // 0..3

    for (int s = 0; s < 14; s++) {
        if (s == 13) asm volatile("cp.async.wait_group 0;" ::: "memory");
        else         asm volatile("cp.async.wait_group 1;" ::: "memory");
        __syncthreads();
        const __nv_bfloat16* Ab = As[s & 1];
        const __nv_bfloat16* Bb = Bs[s & 1];
#pragma unroll
        for (int kk = 0; kk < 2; kk++) {
            uint32_t afr[4][4], bfr[4][2];
            const int cbase = kk*16 + qc*2;
#pragma unroll
            for (int mf = 0; mf < 4; mf++) {
                int row = warpM*64 + mf*16 + qr;
                afr[mf][0] = *(const uint32_t*)&Ab[row*SA_STR + cbase];
                afr[mf][1] = *(const uint32_t*)&Ab[(row+8)*SA_STR + cbase];
                afr[mf][2] = *(const uint32_t*)&Ab[row*SA_STR + cbase + 8];
                afr[mf][3] = *(const uint32_t*)&Ab[(row+8)*SA_STR + cbase + 8];
            }
#pragma unroll
            for (int nf = 0; nf < 4; nf++) {
                int nn = warpN*32 + nf*8 + qr;
                bfr[nf][0] = *(const uint32_t*)&Bb[nn*SA_STR + cbase];
                bfr[nf][1] = *(const uint32_t*)&Bb[nn*SA_STR + cbase + 8];
            }
#pragma unroll
            for (int mf = 0; mf < 4; mf++)
#pragma unroll
                for (int nf = 0; nf < 4; nf++) {
                    asm volatile(
                        "mma.sync.aligned.m16n8k16.row.col.f32.bf16.bf16.f32 "
                        "{%0,%1,%2,%3}, {%4,%5,%6,%7}, {%8,%9}, {%0,%1,%2,%3};"
                        : "+f"(acc[mf][nf][0]), "+f"(acc[mf][nf][1]),
                          "+f"(acc[mf][nf][2]), "+f"(acc[mf][nf][3])
                        : "r"(afr[mf][0]), "r"(afr[mf][1]), "r"(afr[mf][2]), "r"(afr[mf][3]),
                          "r"(bfr[nf][0]), "r"(bfr[nf][1]));
                }
        }
        __syncthreads();
        if (s + 2 < 14) {
            if (s & 1) load_tile(sA1, sB1, Asrc, Bsrc, s + 2, tid);
            else       load_tile(sA0, sB0, Asrc, Bsrc, s + 2, tid);
            CP_COMMIT();
        }
    }

    // epilogue: + bias, direct stores
#pragma unroll
    for (int mf = 0; mf < 4; mf++) {
        int row0 = m0 + warpM*64 + mf*16 + qr;
#pragma unroll
        for (int nf = 0; nf < 4; nf++) {
            int cl = warpN*32 + nf*8 + qc*2;
            float b0 = bias_s[cl], b1 = bias_s[cl + 1];
            float2 o0 = make_float2(acc[mf][nf][0] + b0, acc[mf][nf][1] + b1);
            float2 o1 = make_float2(acc[mf][nf][2] + b0, acc[mf][nf][3] + b1);
            *(float2*)(g_votes + (size_t)row0*1024 + n0 + cl) = o0;
            *(float2*)(g_votes + (size_t)(row0+8)*1024 + n0 + cl) = o1;
        }
    }
}

// ---------------- kernel 2: values + pooling + agreement routing ----------
// Restructured: c2-outer / kp-inner; softmax weights via w_c = 1/std_c
// (the min-std stabilizer cancels identically), so no per-c2 arrays are
// kept live -> ~75 regs -> 3 blocks/SM.
__global__ __launch_bounds__(256, 3) void k_route(const float* __restrict__ Wv,
                                                  const float* __restrict__ bv) {
    __shared__ __align__(16) float wv_s[2048];
    __shared__ float bv_s[256];
    int tid = threadIdx.x;
    for (int i = tid; i < 2048; i += 256) wv_s[i] = Wv[i];
    if (tid < 256) bv_s[tid] = bv[tid];
    __syncthreads();

    int pt   = blockIdx.x * 8 + (tid >> 5);
    int lane = tid & 31;
    int o    = lane >> 2;
    const float* vp = g_votes + pt * 1024;

    u64 vt2[8][2];
#pragma unroll
    for (int c = 0; c < 8; c++) {
        ulonglong2 t = *(const ulonglong2*)(vp + c*128 + lane*4);
        vt2[c][0] = t.x; vt2[c][1] = t.y;
    }

    float av[4] = {0.f, 0.f, 0.f, 0.f};
    float wsum[4] = {0.f, 0.f, 0.f, 0.f};
    float pmax[4] = {-1e30f, -1e30f, -1e30f, -1e30f};
    u64 psum2[2] = {0ULL, 0ULL};

    const float4* wv4 = (const float4*)wv_s;
#pragma unroll
    for (int c2 = 0; c2 < 8; c2++) {
        u64 ks0 = 0ULL, ks1 = 0ULL, kq0 = 0ULL, kq1 = 0ULL;
#pragma unroll
        for (int kp = 0; kp < 4; kp++) {
            int m = kp*8 + c2;
            float4 wa = wv4[(o*32 + m)*2 + 0];
            float4 wb = wv4[(o*32 + m)*2 + 1];
            float bvv = bv_s[o*32 + m];
            u64 bb = pack2(bvv, bvv);
            u64 v0 = bb, v1 = bb, w;
            w = pack2(wa.x, wa.x); v0 = ffma2(w, vt2[0][0], v0); v1 = ffma2(w, vt2[0][1], v1);
            w = pack2(wa.y, wa.y); v0 = ffma2(w, vt2[1][0], v0); v1 = ffma2(w, vt2[1][1], v1);
            w = pack2(wa.z, wa.z); v0 = ffma2(w, vt2[2][0], v0); v1 = ffma2(w, vt2[2][1], v1);
            w = pack2(wa.w, wa.w); v0 = ffma2(w, vt2[3][0], v0); v1 = ffma2(w, vt2[3][1], v1);
            w = pack2(wb.x, wb.x); v0 = ffma2(w, vt2[4][0], v0); v1 = ffma2(w, vt2[4][1], v1);
            w = pack2(wb.y, wb.y); v0 = ffma2(w, vt2[5][0], v0); v1 = ffma2(w, vt2[5][1], v1);
            w = pack2(wb.z, wb.z); v0 = ffma2(w, vt2[6][0], v0); v1 = ffma2(w, vt2[6][1], v1);
            w = pack2(wb.w, wb.w); v0 = ffma2(w, vt2[7][0], v0); v1 = ffma2(w, vt2[7][1], v1);
            ks0 = fadd2(ks0, v0);
            ks1 = fadd2(ks1, v1);
            kq0 = ffma2(v0, v0, kq0);
            kq1 = ffma2(v1, v1, kq1);
            psum2[0] = fadd2(psum2[0], v0);
            psum2[1] = fadd2(psum2[1], v1);
            float f0, f1, f2, f3;
            unpack2(v0, f0, f1); unpack2(v1, f2, f3);
            pmax[0] = fmaxf(pmax[0], f0);
            pmax[1] = fmaxf(pmax[1], f1);
            pmax[2] = fmaxf(pmax[2], f2);
            pmax[3] = fmaxf(pmax[3], f3);
        }
        float ksf[4], kqf[4];
        unpack2(ks0, ksf[0], ksf[1]); unpack2(ks1, ksf[2], ksf[3]);
        unpack2(kq0, kqf[0], kqf[1]); unpack2(kq1, kqf[2], kqf[3]);
#pragma unroll
        for (int j = 0; j < 4; j++) {
            float mu  = ksf[j] * 0.25f;
            float var = fmaxf(kqf[j] * 0.25f - mu*mu, 1e-30f);
            float rs  = rsqrtf(var);       // = 1/std
            av[j]   += mu * rs;
            wsum[j] += rs;
        }
    }

    float sA[4], pMe[4];
    float pf0, pf1, pf2, pf3;
    unpack2(psum2[0], pf0, pf1); unpack2(psum2[1], pf2, pf3);
    pMe[0] = pf0 * (1.f/32.f); pMe[1] = pf1 * (1.f/32.f);
    pMe[2] = pf2 * (1.f/32.f); pMe[3] = pf3 * (1.f/32.f);
#pragma unroll
    for (int j = 0; j < 4; j++) sA[j] = av[j] / wsum[j];

    int off = pt*128 + lane*4;
    *(float4*)(g_sumAtt + off) = make_float4(sA[0], sA[1], sA[2], sA[3]);
    *(float4*)(g_pmax   + off) = make_float4(pmax[0], pmax[1], pmax[2], pmax[3]);
    *(float4*)(g_pmean  + off) = make_float4(pMe[0], pMe[1], pMe[2], pMe[3]);
}

// ---------------- kernel 3: 3D gate conv (3x3x3, pad1) + BN partials -----
__global__ __launch_bounds__(256) void k_gate(const float* __restrict__ Ws) {
    __shared__ float ws_s[54];
    __shared__ float bsum[8], bss[8];
    int tid = threadIdx.x;
    if (tid < 54) ws_s[tid] = Ws[tid];
    if (tid < 8) { bsum[tid] = 0.f; bss[tid] = 0.f; }
    __syncthreads();

    int pt = blockIdx.x * 32 + (tid >> 3);
    int o  = tid & 7;
    int b  = pt >> 10, yx = pt & 1023;
    int y  = yx >> 5,  x  = yx & 31;

    float acc[16];
#pragma unroll
    for (int d = 0; d < 16; d++) acc[d] = 0.f;

    for (int dy = -1; dy <= 1; dy++) {
        int yy = y + dy;
        if ((unsigned)yy >= 32u) continue;
        for (int dx = -1; dx <= 1; dx++) {
            int xx = x + dx;
            if ((unsigned)xx >= 32u) continue;
            int base = ((b << 10) + (yy << 5) + xx)*128 + (o << 4);
            const float4* pm = (const float4*)(g_pmax  + base);
            const float4* pn = (const float4*)(g_pmean + base);
            float rmx[16], rmn[16];
#pragma unroll
            for (int q = 0; q < 4; q++) {
                float4 a = pm[q]; float4 c = pn[q];
                rmx[q*4+0] = a.x; rmx[q*4+1] = a.y; rmx[q*4+2] = a.z; rmx[q*4+3] = a.w;
                rmn[q*4+0] = c.x; rmn[q*4+1] = c.y; rmn[q*4+2] = c.z; rmn[q*4+3] = c.w;
            }
            int wo = (dy+1)*3 + (dx+1);
#pragma unroll
            for (int kz = 0; kz < 3; kz++) {
                float wm = ws_s[kz*9 + wo];
                float wn = ws_s[27 + kz*9 + wo];
#pragma unroll
                for (int d = 0; d < 16; d++) {
                    int s = d + kz - 1;
                    if (s >= 0 && s < 16) acc[d] += wm*rmx[s] + wn*rmn[s];
                }
            }
        }
    }
    float* gp = g_gate + pt*128 + (o << 4);
#pragma unroll
    for (int q = 0; q < 4; q++)
        *(float4*)(gp + q*4) = make_float4(acc[q*4+0], acc[q*4+1], acc[q*4+2], acc[q*4+3]);

    float s1 = 0.f, s2 = 0.f;
#pragma unroll
    for (int d = 0; d < 16; d++) { s1 += acc[d]; s2 += acc[d]*acc[d]; }
    s1 += __shfl_xor_sync(0xffffffffu, s1, 8);
    s2 += __shfl_xor_sync(0xffffffffu, s2, 8);
    s1 += __shfl_xor_sync(0xffffffffu, s1, 16);
    s2 += __shfl_xor_sync(0xffffffffu, s2, 16);
    if ((tid & 31) < 8) { atomicAdd(&bsum[o], s1); atomicAdd(&bss[o], s2); }
    __syncthreads();
    if (tid < 8) {
        g_psumArr[blockIdx.x*8 + tid] = bsum[tid];
        g_pssArr [blockIdx.x*8 + tid] = bss[tid];
    }
}

// ---------------- kernel 3b: BN stats finalize ---------------------------
__global__ void k_bnstats() {
    __shared__ float ss1[256], ss2[256];
    int tid = threadIdx.x;
    int o = tid & 7, seg = tid >> 3;
    float a = 0.f, c = 0.f;
    for (int i = seg*32; i < seg*32 + 32; i++) {
        a += g_psumArr[i*8 + o];
        c += g_pssArr [i*8 + o];
    }
    ss1[tid] = a; ss2[tid] = c;
    __syncthreads();
    if (tid < 8) {
        float A = 0.f, C = 0.f;
        for (int s = 0; s < 32; s++) { A += ss1[s*8 + tid]; C += ss2[s*8 + tid]; }
        const float inv = 1.f / 524288.f;
        float mu = A * inv;
        float var = C * inv - mu*mu;
        g_bnMu[tid]   = mu;
        g_bnRstd[tid] = rsqrtf(var + EPSV);
    }
}

// ---------------- kernel 4: gate apply + LayerNorm + transpose out -------
#define SM4_STRIDE 1025
__global__ __launch_bounds__(256) void k_final(const float* __restrict__ bn_gamma,
                                               const float* __restrict__ bn_beta,
                                               const float* __restrict__ ln_gamma,
                                               const float* __restrict__ ln_beta,
                                               float* __restrict__ out) {
    extern __shared__ float sm4[];
    const int RED = 16*SM4_STRIDE;
    int tid = threadIdx.x;
    int b = blockIdx.x & 31;
    int o = blockIdx.x >> 5;
    float mu = g_bnMu[o], rstd = g_bnRstd[o];
    float gam = bn_gamma[0], bet = bn_beta[0];

    int d   = tid & 15;
    int yxb = tid >> 4;
    const float* gp = g_gate   + (b << 10)*128 + (o << 4) + d;
    const float* sp = g_sumAtt + (b << 10)*128 + (o << 4) + d;
    float s = 0.f, ss = 0.f;
    for (int i = 0; i < 64; i++) {
        int yx = yxb + i*16;
        float gg = gp[yx*128];
        float sa = sp[yx*128];
        float z  = (gg - mu) * rstd * gam + bet;
        float sc = 1.f / (1.f + expf(-z));
        float cn = (1.f + sc) * sa;
        sm4[d*SM4_STRIDE + yx] = cn;
        s += cn; ss += cn*cn;
    }
#pragma unroll
    for (int off = 16; off >= 1; off >>= 1) {
        s  += __shfl_xor_sync(0xffffffffu, s,  off);
        ss += __shfl_xor_sync(0xffffffffu, ss, off);
    }
    int wid = tid >> 5;
    if ((tid & 31) == 0) { sm4[RED + wid] = s; sm4[RED + 8 + wid] = ss; }
    __syncthreads();
    if (tid == 0) {
        float S = 0.f, Q = 0.f;
        for (int w = 0; w < 8; w++) { S += sm4[RED + w]; Q += sm4[RED + 8 + w]; }
        const float inv = 1.f / 16384.f;
        float m = S * inv;
        float var = Q * inv - m*m;
        sm4[RED + 16] = m;
        sm4[RED + 17] = rsqrtf(var + EPSV);
    }
    __syncthreads();
    float m = sm4[RED + 16], r = sm4[RED + 17];
    float* ob = out + ((o*32 + b) << 14);
    for (int i = 0; i < 64; i++) {
        int idx = i*256 + tid;
        float v = sm4[(idx >> 10)*SM4_STRIDE + (idx & 1023)];
        ob[idx] = (v - m) * r * ln_gamma[idx] + ln_beta[idx];
    }
}

// ---------------- launch ------------------------------------------------
extern "C" void kernel_launch(void* const* d_in, const int* in_sizes, int n_in,
                              void* d_out, int out_size) {
    const float* caps = (const float*)d_in[0];
    const float* Wt   = (const float*)d_in[1];
    const float* bt   = (const float*)d_in[2];
    const float* Wv   = (const float*)d_in[3];
    const float* bv   = (const float*)d_in[4];
    const float* Ws   = (const float*)d_in[5];
    const float* bng  = (const float*)d_in[6];
    const float* bnb  = (const float*)d_in[7];
    const float* lng  = (const float*)d_in[8];
    const float* lnb  = (const float*)d_in[9];
    float* out = (float*)d_out;

    const int smemA = 8192 + 64*225*4;            // 65792
    const int smem4 = (16*SM4_STRIDE + 32) * 4;
    cudaFuncSetAttribute(k_prepA, cudaFuncAttributeMaxDynamicSharedMemorySize, smemA);
    cudaFuncSetAttribute(k_final, cudaFuncAttributeMaxDynamicSharedMemorySize, smem4);

    k_prepB<<<1792, 256>>>(Wt);
    k_prepA<<<512, 256, smemA>>>(caps);
    k_gemm<<<dim3(8, 256), 256>>>(bt);
    k_route<<<NPTS/8, 256>>>(Wv, bv);
    k_gate<<<NPTS/32, 256>>>(Ws);
    k_bnstats<<<1, 256>>>();
    k_final<<<256, 256, smem4>>>(bng, bnb, lng, lnb, out);
}